// round 8
// baseline (speedup 1.0000x reference)
#include <cuda_runtime.h>
#include <cuda_bf16.h>
#include <cstdint>

// ---------------------------------------------------------------------------
// GraphAutoencoder:
//   h   = x @ W_enc                                    [N, 128]
//   deg = in-degree(dst) + 1 (self loop); dinv = rsqrt(deg)
//   enc = sum_{e:(s->d)} h[s]*dinv[s]*dinv[d]  + h[i]*dinv[i]^2 + b_enc
//   out = sigmoid(enc @ W_dec + b_dec)                 [N, N]
// Decoder: tf32 mma.sync (m16n8k8) tensor-core GEMM.
// (tcgen05 is unreachable: harness lowers via compute_103 PTX, where ptxas
//  rejects tcgen05.* — sm_103a-variant instructions.)
// ---------------------------------------------------------------------------

#define N_NODES  10000
#define MAX_E    320000
#define IN_DIM   512
#define HID      128

__device__ __align__(16) float g_h[N_NODES * HID];
__device__ __align__(16) float g_enc[N_NODES * HID];
__device__ float g_deg[N_NODES];
__device__ float g_dinv[N_NODES];
__device__ int   g_eidx[2 * MAX_E];
__device__ int   g_is64;

// ========================== 0) edge dtype handling =========================
__global__ void detect_kernel(const void* __restrict__ e)
{
    const unsigned long long* p = (const unsigned long long*)e;
    int ok64 = 1;
    for (int i = 0; i < 128; ++i) {
        unsigned long long v = p[(size_t)i * 2499];
        if (v >= (1ull << 31)) ok64 = 0;
    }
    g_is64 = ok64;
}

__global__ void convert_edges_kernel(const void* __restrict__ e, int E)
{
    int t = blockIdx.x * blockDim.x + threadIdx.x;
    if (t >= 2 * E) return;
    int v;
    if (g_is64) v = (int)((const long long*)e)[t];
    else        v = ((const int*)e)[t];
    g_eidx[t] = v;
}

// ========================== 1) encoder GEMM ================================
__global__ void encode_kernel(const float* __restrict__ x,
                              const float* __restrict__ W,
                              int M)
{
    int j   = threadIdx.x;
    int row = blockIdx.x * blockDim.y + threadIdx.y;
    if (row >= M) return;
    const float* xr = x + (size_t)row * IN_DIM;
    float acc = 0.0f;
#pragma unroll 8
    for (int k = 0; k < IN_DIM; ++k)
        acc = fmaf(__ldg(xr + k), __ldg(W + k * HID + j), acc);
    g_h[(size_t)row * HID + j] = acc;
}

// ========================== 2) normalization ===============================
__global__ void deg_init_kernel(int M)
{
    int i = blockIdx.x * blockDim.x + threadIdx.x;
    if (i < M) g_deg[i] = 1.0f;
}
__global__ void deg_count_kernel(int E)
{
    int t = blockIdx.x * blockDim.x + threadIdx.x;
    if (t >= E) return;
    int d = g_eidx[E + t];
    if (d >= 0 && d < N_NODES) atomicAdd(&g_deg[d], 1.0f);
}
__global__ void dinv_kernel(int M)
{
    int i = blockIdx.x * blockDim.x + threadIdx.x;
    if (i < M) g_dinv[i] = rsqrtf(g_deg[i]);
}
__global__ void enc_init_kernel(const float* __restrict__ b_enc, int M)
{
    int t = blockIdx.x * blockDim.x + threadIdx.x;
    if (t >= M * HID) return;
    int i = t >> 7;
    int j = t & (HID - 1);
    float di = g_dinv[i];
    g_enc[t] = g_h[t] * di * di + b_enc[j];
}

// ========================== 4) edge scatter ================================
__global__ void scatter_kernel(int E)
{
    int warp = (blockIdx.x * blockDim.x + threadIdx.x) >> 5;
    int lane = threadIdx.x & 31;
    if (warp >= E) return;
    int s = g_eidx[warp];
    int d = g_eidx[E + warp];
    if ((unsigned)s >= N_NODES || (unsigned)d >= N_NODES) return;
    float norm = g_dinv[s] * g_dinv[d];
    float4 v = reinterpret_cast<const float4*>(g_h)[(size_t)s * (HID / 4) + lane];
    float* p = g_enc + (size_t)d * HID + lane * 4;
    asm volatile("red.global.add.v4.f32 [%0], {%1, %2, %3, %4};"
                 :: "l"(p), "f"(v.x * norm), "f"(v.y * norm),
                    "f"(v.z * norm), "f"(v.w * norm)
                 : "memory");
}

// ========================== 5) decoder: tf32 mma.sync GEMM =================
// CTA tile 128(M) x 128(N), K=128 in one smem stage.
// 8 warps: 4 (M) x 2 (N); warp tile 32 x 64; m16n8k8 fragments.
// Smem: As[m][k], Bs[n][k], stride 132 (pad 4) -> conflict-free frag loads.
#define DEC_BM   128
#define DEC_BN   128
#define DEC_LDS  132
#define DEC_SMEM_BYTES (2 * 128 * DEC_LDS * 4)   // 135168

__device__ __forceinline__ uint32_t f2tf32(float f) {
    uint32_t u;
    asm("cvt.rna.tf32.f32 %0, %1;" : "=r"(u) : "f"(f));
    return u;
}

__device__ __forceinline__ void mma_16x8x8(float* c, const uint32_t* a,
                                           const uint32_t* b) {
    asm volatile(
        "mma.sync.aligned.m16n8k8.row.col.f32.tf32.tf32.f32 "
        "{%0, %1, %2, %3}, {%4, %5, %6, %7}, {%8, %9}, {%0, %1, %2, %3};"
        : "+f"(c[0]), "+f"(c[1]), "+f"(c[2]), "+f"(c[3])
        : "r"(a[0]), "r"(a[1]), "r"(a[2]), "r"(a[3]),
          "r"(b[0]), "r"(b[1]));
}

__global__ __launch_bounds__(256, 1)
void decode_tc_kernel(const float* __restrict__ Wd,
                      const float* __restrict__ bd,
                      float* __restrict__ out,
                      int M, int N)
{
    extern __shared__ uint32_t dsm[];
    uint32_t (*As)[DEC_LDS] = (uint32_t(*)[DEC_LDS])dsm;
    uint32_t (*Bs)[DEC_LDS] = (uint32_t(*)[DEC_LDS])(dsm + 128 * DEC_LDS);

    const int tid  = threadIdx.x;
    const int w    = tid >> 5;
    const int lane = tid & 31;
    const int g    = lane >> 2;     // group 0..7
    const int q    = lane & 3;      // quad  0..3
    const int wm   = w & 3;         // warp M index (0..3)
    const int wn   = w >> 2;        // warp N index (0..1)
    const int m0   = blockIdx.y * DEC_BM;
    const int n0   = blockIdx.x * DEC_BN;

    // --- stage A: enc[m0+m][k] -> As[m][k] (tf32), coalesced reads ---
#pragma unroll 8
    for (int idx = tid; idx < 128 * 128; idx += 256) {
        int m = idx >> 7;
        int k = idx & 127;
        float v = (m0 + m < M) ? g_enc[(size_t)(m0 + m) * HID + k] : 0.0f;
        As[m][k] = f2tf32(v);
    }
    // --- stage B: Wd[k][n0+n] -> Bs[n][k] (tf32), coalesced reads ---
#pragma unroll 8
    for (int idx = tid; idx < 128 * 128; idx += 256) {
        int k = idx >> 7;
        int n = idx & 127;
        float v = (n0 + n < N) ? Wd[(size_t)k * N + n0 + n] : 0.0f;
        Bs[n][k] = f2tf32(v);
    }
    __syncthreads();

    // --- mainloop: 16 k-steps of 8 ---
    float acc[2][8][4];
#pragma unroll
    for (int i = 0; i < 2; ++i)
#pragma unroll
        for (int j = 0; j < 8; ++j)
#pragma unroll
            for (int r = 0; r < 4; ++r) acc[i][j][r] = 0.0f;

#pragma unroll
    for (int ks = 0; ks < 16; ++ks) {
        const int kb = ks * 8;
        uint32_t a[2][4];
#pragma unroll
        for (int i = 0; i < 2; ++i) {
            int r = wm * 32 + i * 16 + g;
            a[i][0] = As[r][kb + q];
            a[i][1] = As[r + 8][kb + q];
            a[i][2] = As[r][kb + q + 4];
            a[i][3] = As[r + 8][kb + q + 4];
        }
        uint32_t b[8][2];
#pragma unroll
        for (int j = 0; j < 8; ++j) {
            int c = wn * 64 + j * 8 + g;
            b[j][0] = Bs[c][kb + q];
            b[j][1] = Bs[c][kb + q + 4];
        }
#pragma unroll
        for (int i = 0; i < 2; ++i)
#pragma unroll
            for (int j = 0; j < 8; ++j)
                mma_16x8x8(acc[i][j], a[i], b[j]);
    }

    // --- epilogue: bias + sigmoid + float2 stores ---
#pragma unroll
    for (int i = 0; i < 2; ++i) {
        int row0 = m0 + wm * 32 + i * 16 + g;
        int row1 = row0 + 8;
#pragma unroll
        for (int j = 0; j < 8; ++j) {
            int col = n0 + wn * 64 + j * 8 + q * 2;
            if (col + 1 < N) {
                float b0 = __ldg(bd + col);
                float b1 = __ldg(bd + col + 1);
                float t0 = acc[i][j][0] + b0;
                float t1 = acc[i][j][1] + b1;
                float t2 = acc[i][j][2] + b0;
                float t3 = acc[i][j][3] + b1;
                float v0 = __fdividef(1.0f, 1.0f + __expf(-t0));
                float v1 = __fdividef(1.0f, 1.0f + __expf(-t1));
                float v2 = __fdividef(1.0f, 1.0f + __expf(-t2));
                float v3 = __fdividef(1.0f, 1.0f + __expf(-t3));
                if (row0 < M)
                    *reinterpret_cast<float2*>(&out[(size_t)row0 * N + col]) =
                        make_float2(v0, v1);
                if (row1 < M)
                    *reinterpret_cast<float2*>(&out[(size_t)row1 * N + col]) =
                        make_float2(v2, v3);
            }
        }
    }
}

// ========================== launch =========================================
extern "C" void kernel_launch(void* const* d_in, const int* in_sizes, int n_in,
                              void* d_out, int out_size)
{
    const float* x     = (const float*)d_in[0];
    const void*  ei    = d_in[1];
    const float* W_enc = (const float*)d_in[2];
    const float* b_enc = (const float*)d_in[3];
    const float* W_dec = (const float*)d_in[4];
    const float* b_dec = (const float*)d_in[5];
    float*       out   = (float*)d_out;

    const int M = in_sizes[5];        // 10000
    int E = in_sizes[1] / 2;          // 320000
    if (E > MAX_E) E = MAX_E;

    detect_kernel<<<1, 1>>>(ei);
    convert_edges_kernel<<<(2 * E + 255) / 256, 256>>>(ei, E);

    {
        dim3 blk(HID, 4);
        encode_kernel<<<(M + 3) / 4, blk>>>(x, W_enc, M);
    }
    deg_init_kernel <<<(M + 255) / 256, 256>>>(M);
    deg_count_kernel<<<(E + 255) / 256, 256>>>(E);
    dinv_kernel     <<<(M + 255) / 256, 256>>>(M);
    enc_init_kernel <<<(M * HID + 255) / 256, 256>>>(b_enc, M);
    {
        int wpb = 256 / 32;
        scatter_kernel<<<(E + wpb - 1) / wpb, 256>>>(E);
    }
    {
        static int smem_set = 0;
        if (!smem_set) {
            cudaFuncSetAttribute(decode_tc_kernel,
                                 cudaFuncAttributeMaxDynamicSharedMemorySize,
                                 DEC_SMEM_BYTES);
            smem_set = 1;
        }
        dim3 grid((M + DEC_BN - 1) / DEC_BN, (M + DEC_BM - 1) / DEC_BM);
        decode_tc_kernel<<<grid, 256, DEC_SMEM_BYTES>>>(W_dec, b_dec, out, M, M);
    }
}

// round 9
// speedup vs baseline: 1.3313x; 1.3313x over previous
#include <cuda_runtime.h>
#include <cuda_bf16.h>
#include <cstdint>

// ---------------------------------------------------------------------------
// GraphAutoencoder (all-SIMT fp32, f32x2-packed FMA pipe):
//   h   = x @ W_enc                                    [N, 128]
//   deg = in-degree(dst) + 1 (self loop); dinv = rsqrt(deg)
//   enc = sum_{e:(s->d)} h[s]*dinv[s]*dinv[d] + h[i]*dinv[i]^2 + b_enc
//   out = sigmoid(enc @ W_dec + b_dec)                 [N, N]
// tcgen05 unreachable (compute_103 PTX target rejects it); legacy mma.sync
// measured at FFMA-rate (R8) -> decoder stays on the f32x2 path, optimized
// for smem-crossbar conflicts (the R6 bottleneck).
// ---------------------------------------------------------------------------

#define N_NODES  10000
#define MAX_E    320000
#define IN_DIM   512
#define HID      128

__device__ __align__(16) float g_h[N_NODES * HID];
__device__ __align__(16) float g_enc[N_NODES * HID];
__device__ float g_deg[N_NODES];
__device__ float g_dinv[N_NODES];
__device__ int   g_eidx[2 * MAX_E];
__device__ int   g_is64;

// ========================== 0) edge dtype handling =========================
__global__ void detect_kernel(const void* __restrict__ e)
{
    const unsigned long long* p = (const unsigned long long*)e;
    int ok64 = 1;
    for (int i = 0; i < 128; ++i) {
        unsigned long long v = p[(size_t)i * 2499];
        if (v >= (1ull << 31)) ok64 = 0;
    }
    g_is64 = ok64;
}

// convert edges to int32 + initialize degree (self-loop = 1)
__global__ void convert_edges_kernel(const void* __restrict__ e, int E, int M)
{
    int t = blockIdx.x * blockDim.x + threadIdx.x;
    if (t < M) g_deg[t] = 1.0f;
    if (t >= 2 * E) return;
    int v;
    if (g_is64) v = (int)((const long long*)e)[t];
    else        v = ((const int*)e)[t];
    g_eidx[t] = v;
}

// ========================== 2) normalization ===============================
__global__ void deg_count_kernel(int E)
{
    int t = blockIdx.x * blockDim.x + threadIdx.x;
    if (t >= E) return;
    int d = g_eidx[E + t];
    if (d >= 0 && d < N_NODES) atomicAdd(&g_deg[d], 1.0f);
}
__global__ void dinv_kernel(int M)
{
    int i = blockIdx.x * blockDim.x + threadIdx.x;
    if (i < M) g_dinv[i] = rsqrtf(g_deg[i]);
}
__global__ void enc_init_kernel(const float* __restrict__ b_enc, int M)
{
    int t = blockIdx.x * blockDim.x + threadIdx.x;
    if (t >= M * HID) return;
    int i = t >> 7;
    int j = t & (HID - 1);
    float di = g_dinv[i];
    g_enc[t] = g_h[t] * di * di + b_enc[j];
}

// ========================== 4) edge scatter ================================
__global__ void scatter_kernel(int E)
{
    int warp = (blockIdx.x * blockDim.x + threadIdx.x) >> 5;
    int lane = threadIdx.x & 31;
    if (warp >= E) return;
    int s = g_eidx[warp];
    int d = g_eidx[E + warp];
    if ((unsigned)s >= N_NODES || (unsigned)d >= N_NODES) return;
    float norm = g_dinv[s] * g_dinv[d];
    float4 v = reinterpret_cast<const float4*>(g_h)[(size_t)s * (HID / 4) + lane];
    float* p = g_enc + (size_t)d * HID + lane * 4;
    asm volatile("red.global.add.v4.f32 [%0], {%1, %2, %3, %4};"
                 :: "l"(p), "f"(v.x * norm), "f"(v.y * norm),
                    "f"(v.z * norm), "f"(v.w * norm)
                 : "memory");
}

// ========================== 1) encoder GEMM (f32x2 tiled) ==================
// h[M,128] = x[M,512] @ W_enc[512,128].  BM=128, BN=128(=HID), BK=8.
#define EN_BK 8
__global__ __launch_bounds__(256)
void encode_gemm_kernel(const float* __restrict__ A,   // x
                        const float* __restrict__ B,   // W_enc
                        int M)
{
    __shared__ float As[EN_BK][128];
    __shared__ float Bs[EN_BK][128];

    const int tid = threadIdx.x;
    const int m0  = blockIdx.y * 128;

    const int aRow = tid >> 1;
    const int aCol = (tid & 1) * 4;
    const int bRow = tid >> 5;
    const int bCol = (tid & 31) * 4;
    const int tr = tid >> 4;
    const int tc = tid & 15;
    const bool aOK = (m0 + aRow < M);

    unsigned long long acc[8][4];
#pragma unroll
    for (int i = 0; i < 8; ++i)
#pragma unroll
        for (int j = 0; j < 4; ++j) acc[i][j] = 0ull;

    for (int kk = 0; kk < IN_DIM; kk += EN_BK) {
        float4 av = make_float4(0.f, 0.f, 0.f, 0.f);
        if (aOK)
            av = *reinterpret_cast<const float4*>(
                     &A[(size_t)(m0 + aRow) * IN_DIM + kk + aCol]);
        As[aCol + 0][aRow] = av.x;
        As[aCol + 1][aRow] = av.y;
        As[aCol + 2][aRow] = av.z;
        As[aCol + 3][aRow] = av.w;
        float4 bv = *reinterpret_cast<const float4*>(
                        &B[(size_t)(kk + bRow) * HID + bCol]);
        *reinterpret_cast<float4*>(&Bs[bRow][bCol]) = bv;
        __syncthreads();

#pragma unroll
        for (int k = 0; k < EN_BK; ++k) {
            float4 a0 = *reinterpret_cast<const float4*>(&As[k][tr * 8]);
            float4 a1 = *reinterpret_cast<const float4*>(&As[k][tr * 8 + 4]);
            float4 b0 = *reinterpret_cast<const float4*>(&Bs[k][tc * 8]);
            float4 b1 = *reinterpret_cast<const float4*>(&Bs[k][tc * 8 + 4]);
            unsigned long long bp[4];
            asm("mov.b64 %0, {%1, %2};" : "=l"(bp[0]) : "f"(b0.x), "f"(b0.y));
            asm("mov.b64 %0, {%1, %2};" : "=l"(bp[1]) : "f"(b0.z), "f"(b0.w));
            asm("mov.b64 %0, {%1, %2};" : "=l"(bp[2]) : "f"(b1.x), "f"(b1.y));
            asm("mov.b64 %0, {%1, %2};" : "=l"(bp[3]) : "f"(b1.z), "f"(b1.w));
            float a[8] = {a0.x, a0.y, a0.z, a0.w, a1.x, a1.y, a1.z, a1.w};
#pragma unroll
            for (int i = 0; i < 8; ++i) {
                unsigned long long ap;
                asm("mov.b64 %0, {%1, %2};" : "=l"(ap) : "f"(a[i]), "f"(a[i]));
#pragma unroll
                for (int j = 0; j < 4; ++j)
                    asm("fma.rn.f32x2 %0, %1, %2, %0;"
                        : "+l"(acc[i][j]) : "l"(ap), "l"(bp[j]));
            }
        }
        __syncthreads();
    }

#pragma unroll
    for (int i = 0; i < 8; ++i) {
        int row = m0 + tr * 8 + i;
        if (row >= M) continue;
        float v[8];
#pragma unroll
        for (int j = 0; j < 4; ++j) {
            float lo, hi;
            asm("mov.b64 {%0, %1}, %2;" : "=f"(lo), "=f"(hi) : "l"(acc[i][j]));
            v[2 * j] = lo; v[2 * j + 1] = hi;
        }
        size_t base = (size_t)row * HID + tc * 8;
        *reinterpret_cast<float4*>(&g_h[base]) =
            make_float4(v[0], v[1], v[2], v[3]);
        *reinterpret_cast<float4*>(&g_h[base + 4]) =
            make_float4(v[4], v[5], v[6], v[7]);
    }
}

// ========================== 5) decoder GEMM (f32x2, full-K stage) ==========
// out = sigmoid(enc @ W_dec + b_dec).  BM=BN=128, K=128 staged once.
// As[k][m] floats (64 KB).  Bs2 = u64 pairs, layout [k][j][tc] (64 KB):
//   Bs2[k*64 + j*16 + tc] = (Wd[k][n0+tc*8+2j], Wd[k][n0+tc*8+2j+1])
// Mainloop B reads: 4x LDS.64, banks 0..31 exactly once -> conflict-free,
// and bp[] comes out pre-packed (no mov.b64 for B).
__global__ __launch_bounds__(256, 1)
void decode_kernel(const float* __restrict__ Wd,
                   const float* __restrict__ bd,
                   float* __restrict__ out,
                   int M, int N)
{
    extern __shared__ float dsm[];
    float              (*As)[128] = (float(*)[128])dsm;            // [128][128]
    unsigned long long* Bs2 = (unsigned long long*)(dsm + 128 * 128);

    const int tid = threadIdx.x;
    const int m0  = blockIdx.y * 128;
    const int n0  = blockIdx.x * 128;
    const int tr  = tid >> 4;
    const int tc  = tid & 15;
    const bool fullN = (n0 + 128 <= N);

    // --- stage A (transpose): thread -> row m=tid>>1, half (tid&1)*4 ---
    {
        const int m   = tid >> 1;
        const int cb  = (tid & 1) * 4;
        const bool ok = (m0 + m < M);
        const float* src = &g_enc[(size_t)(m0 + m) * HID];
#pragma unroll
        for (int kk = 0; kk < 16; ++kk) {
            int col = kk * 8 + cb;
            float4 av = make_float4(0.f, 0.f, 0.f, 0.f);
            if (ok) av = *reinterpret_cast<const float4*>(src + col);
            As[col + 0][m] = av.x;
            As[col + 1][m] = av.y;
            As[col + 2][m] = av.z;
            As[col + 3][m] = av.w;
        }
    }
    // --- stage B as packed pairs ---
#pragma unroll
    for (int jj = 0; jj < 16; ++jj) {
        int idx4 = jj * 256 + tid;        // 4096 float4 total
        int k    = idx4 >> 5;
        int nq   = idx4 & 31;
        float4 bv;
        if (fullN) {
            bv = *reinterpret_cast<const float4*>(
                     &Wd[(size_t)k * N + n0 + nq * 4]);
        } else {
            float t[4];
#pragma unroll
            for (int i = 0; i < 4; ++i) {
                int c = n0 + nq * 4 + i;
                t[i] = (c < N) ? Wd[(size_t)k * N + c] : 0.f;
            }
            bv = make_float4(t[0], t[1], t[2], t[3]);
        }
        unsigned long long p0, p1;
        asm("mov.b64 %0, {%1, %2};" : "=l"(p0) : "f"(bv.x), "f"(bv.y));
        asm("mov.b64 %0, {%1, %2};" : "=l"(p1) : "f"(bv.z), "f"(bv.w));
        int u0 = k * 64 + ((nq & 1) * 2) * 16 + (nq >> 1);
        Bs2[u0]      = p0;
        Bs2[u0 + 16] = p1;
    }
    __syncthreads();

    // --- mainloop: 128 k-steps ---
    unsigned long long acc[8][4];
#pragma unroll
    for (int i = 0; i < 8; ++i)
#pragma unroll
        for (int j = 0; j < 4; ++j) acc[i][j] = 0ull;

#pragma unroll 8
    for (int k = 0; k < 128; ++k) {
        float4 a0 = *reinterpret_cast<const float4*>(&As[k][tr * 8]);
        float4 a1 = *reinterpret_cast<const float4*>(&As[k][tr * 8 + 4]);
        unsigned long long bp[4];
        const unsigned long long* brow = Bs2 + k * 64 + tc;
        bp[0] = brow[0];
        bp[1] = brow[16];
        bp[2] = brow[32];
        bp[3] = brow[48];
        float a[8] = {a0.x, a0.y, a0.z, a0.w, a1.x, a1.y, a1.z, a1.w};
#pragma unroll
        for (int i = 0; i < 8; ++i) {
            unsigned long long ap;
            asm("mov.b64 %0, {%1, %2};" : "=l"(ap) : "f"(a[i]), "f"(a[i]));
#pragma unroll
            for (int j = 0; j < 4; ++j)
                asm("fma.rn.f32x2 %0, %1, %2, %0;"
                    : "+l"(acc[i][j]) : "l"(ap), "l"(bp[j]));
        }
    }

    // --- epilogue: bias + sigmoid ---
    float bdv[8];
#pragma unroll
    for (int j = 0; j < 8; ++j) {
        int c = n0 + tc * 8 + j;
        bdv[j] = (c < N) ? __ldg(bd + c) : 0.f;
    }
#pragma unroll
    for (int i = 0; i < 8; ++i) {
        int row = m0 + tr * 8 + i;
        if (row >= M) continue;
        float v[8];
#pragma unroll
        for (int j = 0; j < 4; ++j) {
            float lo, hi;
            asm("mov.b64 {%0, %1}, %2;" : "=f"(lo), "=f"(hi) : "l"(acc[i][j]));
            v[2 * j] = lo; v[2 * j + 1] = hi;
        }
#pragma unroll
        for (int j = 0; j < 8; ++j) {
            float t = v[j] + bdv[j];
            v[j] = __fdividef(1.0f, 1.0f + __expf(-t));
        }
        size_t base = (size_t)row * N + n0 + tc * 8;
        if (fullN) {
            *reinterpret_cast<float4*>(&out[base]) =
                make_float4(v[0], v[1], v[2], v[3]);
            *reinterpret_cast<float4*>(&out[base + 4]) =
                make_float4(v[4], v[5], v[6], v[7]);
        } else {
#pragma unroll
            for (int j = 0; j < 8; ++j) {
                int c = n0 + tc * 8 + j;
                if (c < N) out[(size_t)row * N + c] = v[j];
            }
        }
    }
}

#define DEC_SMEM_BYTES (128 * 128 * 4 + 128 * 64 * 8)   // 131072

// ========================== launch =========================================
extern "C" void kernel_launch(void* const* d_in, const int* in_sizes, int n_in,
                              void* d_out, int out_size)
{
    const float* x     = (const float*)d_in[0];
    const void*  ei    = d_in[1];
    const float* W_enc = (const float*)d_in[2];
    const float* b_enc = (const float*)d_in[3];
    const float* W_dec = (const float*)d_in[4];
    const float* b_dec = (const float*)d_in[5];
    float*       out   = (float*)d_out;

    const int M = in_sizes[5];        // 10000
    int E = in_sizes[1] / 2;          // 320000
    if (E > MAX_E) E = MAX_E;

    detect_kernel<<<1, 1>>>(ei);
    convert_edges_kernel<<<(2 * E + 255) / 256, 256>>>(ei, E, M);

    {   // encoder GEMM
        dim3 grid(1, (M + 127) / 128);
        encode_gemm_kernel<<<grid, 256>>>(x, W_enc, M);
    }
    deg_count_kernel<<<(E + 255) / 256, 256>>>(E);
    dinv_kernel     <<<(M + 255) / 256, 256>>>(M);
    enc_init_kernel <<<(M * HID + 255) / 256, 256>>>(b_enc, M);
    {
        int wpb = 256 / 32;
        scatter_kernel<<<(E + wpb - 1) / wpb, 256>>>(E);
    }
    {
        static int smem_set = 0;
        if (!smem_set) {
            cudaFuncSetAttribute(decode_kernel,
                                 cudaFuncAttributeMaxDynamicSharedMemorySize,
                                 DEC_SMEM_BYTES);
            smem_set = 1;
        }
        dim3 grid((M + 127) / 128, (M + 127) / 128);
        decode_kernel<<<grid, 256, DEC_SMEM_BYTES>>>(W_dec, b_dec, out, M, M);
    }
}